// round 12
// baseline (speedup 1.0000x reference)
#include <cuda_runtime.h>
#include <cstdint>

#define D_IN   128
#define D_OUT  64
#define D_EDGE 11
#define NMAX   100000
#define EMAX   1000000
#define NEG_SLOPE 0.2f

// Scratch: ONLY referenced from device code (host-side use of a __device__
// symbol passes the host shadow address; ATS silently dereferences it).
__device__ float g_xl[(size_t)NMAX * D_OUT];     // x @ W_l
__device__ float g_xr[(size_t)NMAX * D_OUT];     // x @ W_r
__device__ float g_lsum[(size_t)NMAX * 12];      // [0..10]=sum attr, [11]=deg
__device__ float g_denom[NMAX];                  // sum of exp(logit) per dst
__device__ int2  g_sd[EMAX];                     // decoded (src, dst)
__device__ int   g_is64;
__device__ int   g_diag;

// ---------------------------------------------------------------------------
// Zero output + accumulators; detect int32 vs int64 edge_index (int64 values
// < 2^31 -> hi words of first 64 entries all zero).
// ---------------------------------------------------------------------------
__global__ void init_kernel(float* __restrict__ out, int out_total,
                            const int* __restrict__ ei, int E, int n) {
    int stride = gridDim.x * blockDim.x;
    int tid0 = blockIdx.x * blockDim.x + threadIdx.x;
    if (tid0 == 0) {
        g_diag = 0;
        int nz_hi = 0;
        int lim = (E > 64) ? 64 : E;
        for (int k = 0; k < lim; k++)
            if (ei[2 * k + 1] != 0) nz_hi++;
        g_is64 = (nz_hi == 0) ? 1 : 0;
    }
    for (int i = tid0; i < out_total; i += stride) out[i] = 0.0f;
    int total = n * 12;
    for (int i = tid0; i < total; i += stride) {
        g_lsum[i] = 0.0f;
        if (i < n) g_denom[i] = 0.0f;
    }
}

__global__ void set_diag_kernel(int bits) {
    if (threadIdx.x == 0) atomicOr(&g_diag, bits);
}

// Decode edge_index -> (src,dst) int2, bounds-checked.
__global__ void decode_kernel(const int* __restrict__ ei, int E, int n) {
    const int is64 = g_is64;
    int stride = gridDim.x * blockDim.x;
    for (int i = blockIdx.x * blockDim.x + threadIdx.x; i < E; i += stride) {
        int s, d;
        if (is64) { s = ei[2 * i];  d = ei[2 * E + 2 * i]; }
        else      { s = ei[i];      d = ei[E + i]; }
        if ((unsigned)s >= (unsigned)n) { atomicOr(&g_diag, 4); s = 0; }
        if ((unsigned)d >= (unsigned)n) { atomicOr(&g_diag, 4); d = 0; }
        g_sd[i] = make_int2(s, d);
    }
}

__global__ void diag_apply_kernel(float* __restrict__ out, int total) {
    const int diag = g_diag;
    if (diag == 0) return;
    float v = 0.f;
    if (diag & 4) v = 1e16f;
    if (diag & 8) v = 1e20f;
    int stride = gridDim.x * blockDim.x;
    for (int i = blockIdx.x * blockDim.x + threadIdx.x; i < total; i += stride)
        out[i] = v;
}

// ---------------------------------------------------------------------------
// GEMM (R9, measured 59.1us): g_x{l,r}[n,64] = x[n,128] @ W[128,64].
// Bank-conflict-free: thread cg reads smem words cg*4 / 32+cg*4.
// ---------------------------------------------------------------------------
__global__ __launch_bounds__(256) void gemm_kernel(
    const float* __restrict__ x, const float* __restrict__ W,
    int n, int which)
{
    float* __restrict__ out = which ? g_xr : g_xl;   // device-side symbol

    __shared__ float sW[D_IN * D_OUT];  // 32 KB
    for (int i = threadIdx.x; i < D_IN * D_OUT / 4; i += 256) {
        reinterpret_cast<float4*>(sW)[i] = reinterpret_cast<const float4*>(W)[i];
    }
    __syncthreads();

    const int cg   = threadIdx.x & 7;
    const int rg   = threadIdx.x >> 3;
    const int row0 = blockIdx.x * 128 + rg * 4;
    const float4* sW4 = reinterpret_cast<const float4*>(sW);

    float acc0[4][4], acc1[4][4];
#pragma unroll
    for (int r = 0; r < 4; r++)
#pragma unroll
        for (int c = 0; c < 4; c++) { acc0[r][c] = 0.f; acc1[r][c] = 0.f; }

    for (int k = 0; k < D_IN; k += 4) {
        float xk[4][4];
#pragma unroll
        for (int r = 0; r < 4; r++) {
            int row = row0 + r;
            float4 v = make_float4(0.f, 0.f, 0.f, 0.f);
            if (row < n)
                v = *reinterpret_cast<const float4*>(x + (size_t)row * D_IN + k);
            xk[r][0] = v.x; xk[r][1] = v.y; xk[r][2] = v.z; xk[r][3] = v.w;
        }
#pragma unroll
        for (int kk = 0; kk < 4; kk++) {
            const float4 w0 = sW4[(k + kk) * 16 + cg];
            const float4 w1 = sW4[(k + kk) * 16 + 8 + cg];
#pragma unroll
            for (int r = 0; r < 4; r++) {
                const float xv = xk[r][kk];
                acc0[r][0] += xv * w0.x;  acc0[r][1] += xv * w0.y;
                acc0[r][2] += xv * w0.z;  acc0[r][3] += xv * w0.w;
                acc1[r][0] += xv * w1.x;  acc1[r][1] += xv * w1.y;
                acc1[r][2] += xv * w1.z;  acc1[r][3] += xv * w1.w;
            }
        }
    }

#pragma unroll
    for (int r = 0; r < 4; r++) {
        int row = row0 + r;
        if (row < n) {
            *reinterpret_cast<float4*>(out + (size_t)row * D_OUT + cg * 4) =
                make_float4(acc0[r][0], acc0[r][1], acc0[r][2], acc0[r][3]);
            *reinterpret_cast<float4*>(out + (size_t)row * D_OUT + 32 + cg * 4) =
                make_float4(acc1[r][0], acc1[r][1], acc1[r][2], acc1[r][3]);
        }
    }
}

// ---------------------------------------------------------------------------
// Edge pass: 2 edges per warp; 16 lanes x 4 cols. Software-pipelined:
//  - REDs carry NO "memory" clobber (atomics are order-free here), so the
//    compiler may overlap next-iteration loads with current compute/REDs.
//  - sd/attr of iteration i+1 are prefetched before iteration i's compute.
// ---------------------------------------------------------------------------
__device__ __forceinline__ void red_add_v4(float* p, float a, float b, float c, float d) {
    // volatile: must execute; NO memory clobber: no intra-kernel ordering
    // needed (commutative reductions, consumed only after kernel boundary).
    asm volatile("red.global.add.v4.f32 [%0], {%1,%2,%3,%4};"
                 :: "l"(p), "f"(a), "f"(b), "f"(c), "f"(d));
}
__device__ __forceinline__ void red_add_f32(float* p, float a) {
    asm volatile("red.global.add.f32 [%0], %1;" :: "l"(p), "f"(a));
}

__global__ __launch_bounds__(256) void edge_kernel(
    const float* __restrict__ ea,
    const float* __restrict__ We, const float* __restrict__ att,
    float* __restrict__ out, int E)
{
    const int lane   = threadIdx.x & 31;
    const int half   = lane >> 4;
    const int sub    = lane & 15;
    const int cb     = sub * 4;
    const int hbase  = half << 4;
    const int warp   = (blockIdx.x * blockDim.x + threadIdx.x) >> 5;
    const int nwarps = (gridDim.x * blockDim.x) >> 5;

    float4 wev[D_EDGE];
#pragma unroll
    for (int j = 0; j < D_EDGE; j++)
        wev[j] = *reinterpret_cast<const float4*>(We + j * D_OUT + cb);
    const float4 at = *reinterpret_cast<const float4*>(att + cb);

    const int step = nwarps * 2;
    int e0 = warp * 2;
    if (e0 >= E) return;

    // Prologue: load iteration 0's sd/attr.
    int  ec  = (e0 + half < E) ? (e0 + half) : e0;
    int2 sd  = g_sd[ec];
    float av = (sub < D_EDGE) ? __ldg(ea + (size_t)ec * D_EDGE + sub) : 0.f;

    for (; e0 < E; e0 += step) {
        const bool valid = (e0 + half < E);
        const int2 sd_c  = sd;
        const float av_c = av;

        // ---- prefetch next iteration's sd/attr (independent of this one) --
        const int e0n = e0 + step;
        if (e0n < E) {
            const int ecn = (e0n + half < E) ? (e0n + half) : e0n;
            sd = g_sd[ecn];
            av = (sub < D_EDGE) ? __ldg(ea + (size_t)ecn * D_EDGE + sub) : 0.f;
        }

        // ---- gather xl[src], xr[dst] --------------------------------------
        const float4 vl = *reinterpret_cast<const float4*>(
            g_xl + (size_t)sd_c.x * D_OUT + cb);
        const float4 vr = *reinterpret_cast<const float4*>(
            g_xr + (size_t)sd_c.y * D_OUT + cb);

        // Broadcast the 11 attr values to all lanes of this half.
        float aj[D_EDGE];
#pragma unroll
        for (int j = 0; j < D_EDGE; j++)
            aj[j] = __shfl_sync(0xffffffffu, av_c, hbase + j);

        float e0c = 0.f, e1c = 0.f, e2c = 0.f, e3c = 0.f;
#pragma unroll
        for (int j = 0; j < D_EDGE; j++) {
            e0c += aj[j] * wev[j].x;
            e1c += aj[j] * wev[j].y;
            e2c += aj[j] * wev[j].z;
            e3c += aj[j] * wev[j].w;
        }

        float m0 = vl.x + vr.x + e0c;
        float m1 = vl.y + vr.y + e1c;
        float m2 = vl.z + vr.z + e2c;
        float m3 = vl.w + vr.w + e3c;
        m0 = (m0 >= 0.f) ? m0 : NEG_SLOPE * m0;
        m1 = (m1 >= 0.f) ? m1 : NEG_SLOPE * m1;
        m2 = (m2 >= 0.f) ? m2 : NEG_SLOPE * m2;
        m3 = (m3 >= 0.f) ? m3 : NEG_SLOPE * m3;
        float p = m0 * at.x + m1 * at.y + m2 * at.z + m3 * at.w;
#pragma unroll
        for (int o = 8; o > 0; o >>= 1)          // reduce within the half
            p += __shfl_xor_sync(0xffffffffu, p, o);
        const float ex = __expf(p);

        if (valid) {
            red_add_v4(out + (size_t)sd_c.y * D_OUT + cb,
                       ex * vl.x, ex * vl.y, ex * vl.z, ex * vl.w);
            if (sub < 3) {
                const float b0 = (sub == 0) ? aj[0] : (sub == 1) ? aj[4] : aj[8];
                const float b1 = (sub == 0) ? aj[1] : (sub == 1) ? aj[5] : aj[9];
                const float b2 = (sub == 0) ? aj[2] : (sub == 1) ? aj[6] : aj[10];
                const float b3 = (sub == 0) ? aj[3] : (sub == 1) ? aj[7] : 1.0f;
                red_add_v4(&g_lsum[(size_t)sd_c.y * 12 + sub * 4], b0, b1, b2, b3);
            } else if (sub == 3) {
                red_add_f32(&g_denom[sd_c.y], ex);
            }
        }
    }
}

// ---------------------------------------------------------------------------
// Finalize: 2 nodes per warp (16 lanes x 4 cols). Self-loop term + normalize.
// ---------------------------------------------------------------------------
__global__ __launch_bounds__(256) void final_kernel(
    const float* __restrict__ We, const float* __restrict__ att,
    float* __restrict__ out, int n)
{
    const int lane   = threadIdx.x & 31;
    const int half   = lane >> 4;
    const int sub    = lane & 15;
    const int cb     = sub * 4;
    const int warp   = (blockIdx.x * blockDim.x + threadIdx.x) >> 5;
    const int nwarps = (gridDim.x * blockDim.x) >> 5;

    float4 wev[D_EDGE];
#pragma unroll
    for (int j = 0; j < D_EDGE; j++)
        wev[j] = *reinterpret_cast<const float4*>(We + j * D_OUT + cb);
    const float4 at = *reinterpret_cast<const float4*>(att + cb);

    for (int i0 = warp * 2; i0 < n; i0 += nwarps * 2) {
        const int  i     = i0 + half;
        const bool valid = (i < n);
        const int  ic    = valid ? i : i0;

        const float4* lp = reinterpret_cast<const float4*>(g_lsum + (size_t)ic * 12);
        const float4 q0 = lp[0];
        const float4 q1 = lp[1];
        const float4 q2 = lp[2];
        const float inv_deg = 1.0f / fmaxf(q2.w, 1.0f);

        float e0c = q0.x*wev[0].x + q0.y*wev[1].x + q0.z*wev[2].x + q0.w*wev[3].x
                  + q1.x*wev[4].x + q1.y*wev[5].x + q1.z*wev[6].x + q1.w*wev[7].x
                  + q2.x*wev[8].x + q2.y*wev[9].x + q2.z*wev[10].x;
        float e1c = q0.x*wev[0].y + q0.y*wev[1].y + q0.z*wev[2].y + q0.w*wev[3].y
                  + q1.x*wev[4].y + q1.y*wev[5].y + q1.z*wev[6].y + q1.w*wev[7].y
                  + q2.x*wev[8].y + q2.y*wev[9].y + q2.z*wev[10].y;
        float e2c = q0.x*wev[0].z + q0.y*wev[1].z + q0.z*wev[2].z + q0.w*wev[3].z
                  + q1.x*wev[4].z + q1.y*wev[5].z + q1.z*wev[6].z + q1.w*wev[7].z
                  + q2.x*wev[8].z + q2.y*wev[9].z + q2.z*wev[10].z;
        float e3c = q0.x*wev[0].w + q0.y*wev[1].w + q0.z*wev[2].w + q0.w*wev[3].w
                  + q1.x*wev[4].w + q1.y*wev[5].w + q1.z*wev[6].w + q1.w*wev[7].w
                  + q2.x*wev[8].w + q2.y*wev[9].w + q2.z*wev[10].w;
        e0c *= inv_deg; e1c *= inv_deg; e2c *= inv_deg; e3c *= inv_deg;

        const float4 vl = *reinterpret_cast<const float4*>(g_xl + (size_t)ic * D_OUT + cb);
        const float4 vr = *reinterpret_cast<const float4*>(g_xr + (size_t)ic * D_OUT + cb);

        float m0 = vl.x + vr.x + e0c;
        float m1 = vl.y + vr.y + e1c;
        float m2 = vl.z + vr.z + e2c;
        float m3 = vl.w + vr.w + e3c;
        m0 = (m0 >= 0.f) ? m0 : NEG_SLOPE * m0;
        m1 = (m1 >= 0.f) ? m1 : NEG_SLOPE * m1;
        m2 = (m2 >= 0.f) ? m2 : NEG_SLOPE * m2;
        m3 = (m3 >= 0.f) ? m3 : NEG_SLOPE * m3;
        float p = m0 * at.x + m1 * at.y + m2 * at.z + m3 * at.w;
#pragma unroll
        for (int o = 8; o > 0; o >>= 1)
            p += __shfl_xor_sync(0xffffffffu, p, o);
        const float ex = __expf(p);

        if (valid) {
            const float invd = 1.0f / (g_denom[ic] + ex);
            float* op = out + (size_t)ic * D_OUT + cb;
            float4 o = *reinterpret_cast<float4*>(op);
            o.x = (o.x + ex * vl.x) * invd;
            o.y = (o.y + ex * vl.y) * invd;
            o.z = (o.z + ex * vl.z) * invd;
            o.w = (o.w + ex * vl.w) * invd;
            *reinterpret_cast<float4*>(op) = o;
        }
    }
}

// ---------------------------------------------------------------------------
extern "C" void kernel_launch(void* const* d_in, const int* in_sizes, int n_in,
                              void* d_out, int out_size)
{
    const float *x = nullptr, *ea = nullptr, *Wl = nullptr, *Wr = nullptr;
    const float *We = nullptr, *att = nullptr;
    const int   *ei = nullptr;
    long long E = 0;
    int n = 0;

    for (int i = 0; i < n_in; i++) {               // pass 1: edge_attr
        long long s = in_sizes[i];
        if (s > 100000 && s % D_EDGE == 0) { ea = (const float*)d_in[i]; E = s / D_EDGE; }
    }
    for (int i = 0; i < n_in; i++) {               // pass 2: everything else
        long long s = in_sizes[i];
        const void* p = d_in[i];
        if (p == (const void*)ea) continue;
        if      (E > 0 && (s == 2 * E || s == 4 * E)) { ei = (const int*)p; }
        else if (s == D_IN * D_OUT)   { if (!Wl) Wl = (const float*)p; else Wr = (const float*)p; }
        else if (s == D_EDGE * D_OUT) { We  = (const float*)p; }
        else if (s == D_OUT)          { att = (const float*)p; }
        else if (s > 100000 && s % D_IN == 0) { x = (const float*)p; n = (int)(s / D_IN); }
    }

    float* out = (float*)d_out;
    const int total_out = out_size;

    if (!x || !ea || !ei || !Wl || !Wr || !We || !att || n <= 0 || E <= 0 ||
        n > NMAX || E > EMAX) {
        set_diag_kernel<<<1, 32>>>(8);
        diag_apply_kernel<<<512, 256>>>(out, total_out);
        return;
    }
    const int Ei = (int)E;

    init_kernel<<<1024, 256>>>(out, total_out, ei, Ei, n);
    decode_kernel<<<512, 256>>>(ei, Ei, n);

    gemm_kernel<<<(n + 127) / 128, 256>>>(x, Wl, n, 0);  // -> g_xl
    gemm_kernel<<<(n + 127) / 128, 256>>>(x, Wr, n, 1);  // -> g_xr

    edge_kernel<<<4096, 256>>>(ea, We, att, out, Ei);
    final_kernel<<<2048, 256>>>(We, att, out, n);

    diag_apply_kernel<<<512, 256>>>(out, total_out);
}

// round 14
// speedup vs baseline: 1.1897x; 1.1897x over previous
#include <cuda_runtime.h>
#include <cstdint>

#define D_IN   128
#define D_OUT  64
#define D_EDGE 11
#define NMAX   100000
#define EMAX   1000000
#define NEG_SLOPE 0.2f

// Scratch: ONLY referenced from device code (host-side use of a __device__
// symbol passes the host shadow address; ATS silently dereferences it).
__device__ float g_xl[(size_t)NMAX * D_OUT];     // x @ W_l
__device__ float g_xr[(size_t)NMAX * D_OUT];     // x @ W_r
__device__ float g_lsum[(size_t)NMAX * 12];      // [0..10]=sum attr, [11]=deg
__device__ float g_denom[NMAX];                  // sum of exp(logit) per dst
__device__ int2  g_sd[EMAX];                     // decoded (src, dst)
__device__ int   g_is64;
__device__ int   g_diag;

// ---------------------------------------------------------------------------
// Zero output + accumulators; detect int32 vs int64 edge_index (int64 values
// < 2^31 -> hi words of first 64 entries all zero).
// ---------------------------------------------------------------------------
__global__ void init_kernel(float* __restrict__ out, int out_total,
                            const int* __restrict__ ei, int E, int n) {
    int stride = gridDim.x * blockDim.x;
    int tid0 = blockIdx.x * blockDim.x + threadIdx.x;
    if (tid0 == 0) {
        g_diag = 0;
        int nz_hi = 0;
        int lim = (E > 64) ? 64 : E;
        for (int k = 0; k < lim; k++)
            if (ei[2 * k + 1] != 0) nz_hi++;
        g_is64 = (nz_hi == 0) ? 1 : 0;
    }
    for (int i = tid0; i < out_total; i += stride) out[i] = 0.0f;
    int total = n * 12;
    for (int i = tid0; i < total; i += stride) {
        g_lsum[i] = 0.0f;
        if (i < n) g_denom[i] = 0.0f;
    }
}

__global__ void set_diag_kernel(int bits) {
    if (threadIdx.x == 0) atomicOr(&g_diag, bits);
}

// Decode edge_index -> (src,dst) int2, bounds-checked.
__global__ void decode_kernel(const int* __restrict__ ei, int E, int n) {
    const int is64 = g_is64;
    int stride = gridDim.x * blockDim.x;
    for (int i = blockIdx.x * blockDim.x + threadIdx.x; i < E; i += stride) {
        int s, d;
        if (is64) { s = ei[2 * i];  d = ei[2 * E + 2 * i]; }
        else      { s = ei[i];      d = ei[E + i]; }
        if ((unsigned)s >= (unsigned)n) { atomicOr(&g_diag, 4); s = 0; }
        if ((unsigned)d >= (unsigned)n) { atomicOr(&g_diag, 4); d = 0; }
        g_sd[i] = make_int2(s, d);
    }
}

__global__ void diag_apply_kernel(float* __restrict__ out, int total) {
    const int diag = g_diag;
    if (diag == 0) return;
    float v = 0.f;
    if (diag & 4) v = 1e16f;
    if (diag & 8) v = 1e20f;
    int stride = gridDim.x * blockDim.x;
    for (int i = blockIdx.x * blockDim.x + threadIdx.x; i < total; i += stride)
        out[i] = v;
}

// ---------------------------------------------------------------------------
// GEMM (R9, measured 59.1us): g_x{l,r}[n,64] = x[n,128] @ W[128,64].
// Bank-conflict-free: thread cg reads smem words cg*4 / 32+cg*4.
// ---------------------------------------------------------------------------
__global__ __launch_bounds__(256) void gemm_kernel(
    const float* __restrict__ x, const float* __restrict__ W,
    int n, int which)
{
    float* __restrict__ out = which ? g_xr : g_xl;   // device-side symbol

    __shared__ float sW[D_IN * D_OUT];  // 32 KB
    for (int i = threadIdx.x; i < D_IN * D_OUT / 4; i += 256) {
        reinterpret_cast<float4*>(sW)[i] = reinterpret_cast<const float4*>(W)[i];
    }
    __syncthreads();

    const int cg   = threadIdx.x & 7;
    const int rg   = threadIdx.x >> 3;
    const int row0 = blockIdx.x * 128 + rg * 4;
    const float4* sW4 = reinterpret_cast<const float4*>(sW);

    float acc0[4][4], acc1[4][4];
#pragma unroll
    for (int r = 0; r < 4; r++)
#pragma unroll
        for (int c = 0; c < 4; c++) { acc0[r][c] = 0.f; acc1[r][c] = 0.f; }

    for (int k = 0; k < D_IN; k += 4) {
        float xk[4][4];
#pragma unroll
        for (int r = 0; r < 4; r++) {
            int row = row0 + r;
            float4 v = make_float4(0.f, 0.f, 0.f, 0.f);
            if (row < n)
                v = *reinterpret_cast<const float4*>(x + (size_t)row * D_IN + k);
            xk[r][0] = v.x; xk[r][1] = v.y; xk[r][2] = v.z; xk[r][3] = v.w;
        }
#pragma unroll
        for (int kk = 0; kk < 4; kk++) {
            const float4 w0 = sW4[(k + kk) * 16 + cg];
            const float4 w1 = sW4[(k + kk) * 16 + 8 + cg];
#pragma unroll
            for (int r = 0; r < 4; r++) {
                const float xv = xk[r][kk];
                acc0[r][0] += xv * w0.x;  acc0[r][1] += xv * w0.y;
                acc0[r][2] += xv * w0.z;  acc0[r][3] += xv * w0.w;
                acc1[r][0] += xv * w1.x;  acc1[r][1] += xv * w1.y;
                acc1[r][2] += xv * w1.z;  acc1[r][3] += xv * w1.w;
            }
        }
    }

#pragma unroll
    for (int r = 0; r < 4; r++) {
        int row = row0 + r;
        if (row < n) {
            *reinterpret_cast<float4*>(out + (size_t)row * D_OUT + cg * 4) =
                make_float4(acc0[r][0], acc0[r][1], acc0[r][2], acc0[r][3]);
            *reinterpret_cast<float4*>(out + (size_t)row * D_OUT + 32 + cg * 4) =
                make_float4(acc1[r][0], acc1[r][1], acc1[r][2], acc1[r][3]);
        }
    }
}

// ---------------------------------------------------------------------------
// Edge pass (R9 structure): 2 edges per warp; 16 lanes x 4 cols per edge.
// W_e slice lives in SHARED memory (warp-uniform read-only) instead of 44
// registers -> higher occupancy -> more latency hiding.
// ---------------------------------------------------------------------------
__device__ __forceinline__ void red_add_v4(float* p, float a, float b, float c, float d) {
    asm volatile("red.global.add.v4.f32 [%0], {%1,%2,%3,%4};"
                 :: "l"(p), "f"(a), "f"(b), "f"(c), "f"(d) : "memory");
}

__global__ __launch_bounds__(256, 4) void edge_kernel(
    const float* __restrict__ ea,
    const float* __restrict__ We, const float* __restrict__ att,
    float* __restrict__ out, int E)
{
    __shared__ float4 sWe[16 * 13];   // 16 col-slices x 11 rows, stride 13

    const int lane   = threadIdx.x & 31;
    const int half   = lane >> 4;
    const int sub    = lane & 15;
    const int cb     = sub * 4;
    const int hbase  = half << 4;
    const int warp   = (blockIdx.x * blockDim.x + threadIdx.x) >> 5;
    const int nwarps = (gridDim.x * blockDim.x) >> 5;

    // Stage W_e slices: sWe[s*13+j] = We[j][s*4 .. s*4+3]
    for (int i = threadIdx.x; i < 16 * D_EDGE; i += 256) {
        const int s = i / D_EDGE, j = i - s * D_EDGE;
        sWe[s * 13 + j] = *reinterpret_cast<const float4*>(We + j * D_OUT + s * 4);
    }
    __syncthreads();

    const float4 at = *reinterpret_cast<const float4*>(att + cb);
    const int wbase = sub * 13;

    for (int e0 = warp * 2; e0 < E; e0 += nwarps * 2) {
        const int  e     = e0 + half;
        const bool valid = (e < E);
        const int  ec    = valid ? e : e0;

        const int2 sd = g_sd[ec];
        // One warp LDG: lanes 0..10 of each half fetch this edge's attr row.
        const float av = (sub < D_EDGE) ? __ldg(ea + (size_t)ec * D_EDGE + sub) : 0.f;

        const float4 vl = *reinterpret_cast<const float4*>(
            g_xl + (size_t)sd.x * D_OUT + cb);
        const float4 vr = *reinterpret_cast<const float4*>(
            g_xr + (size_t)sd.y * D_OUT + cb);

        // Broadcast the 11 attr values to all lanes (feeds e-term AND lsum).
        float aj[D_EDGE];
#pragma unroll
        for (int j = 0; j < D_EDGE; j++)
            aj[j] = __shfl_sync(0xffffffffu, av, hbase + j);

        float e0c = 0.f, e1c = 0.f, e2c = 0.f, e3c = 0.f;
#pragma unroll
        for (int j = 0; j < D_EDGE; j++) {
            const float4 w = sWe[wbase + j];
            e0c += aj[j] * w.x;
            e1c += aj[j] * w.y;
            e2c += aj[j] * w.z;
            e3c += aj[j] * w.w;
        }

        float m0 = vl.x + vr.x + e0c;
        float m1 = vl.y + vr.y + e1c;
        float m2 = vl.z + vr.z + e2c;
        float m3 = vl.w + vr.w + e3c;
        m0 = (m0 >= 0.f) ? m0 : NEG_SLOPE * m0;
        m1 = (m1 >= 0.f) ? m1 : NEG_SLOPE * m1;
        m2 = (m2 >= 0.f) ? m2 : NEG_SLOPE * m2;
        m3 = (m3 >= 0.f) ? m3 : NEG_SLOPE * m3;
        float p = m0 * at.x + m1 * at.y + m2 * at.z + m3 * at.w;
#pragma unroll
        for (int o = 8; o > 0; o >>= 1)          // reduce within the half
            p += __shfl_xor_sync(0xffffffffu, p, o);
        const float ex = __expf(p);

        if (valid) {
            red_add_v4(out + (size_t)sd.y * D_OUT + cb,
                       ex * vl.x, ex * vl.y, ex * vl.z, ex * vl.w);
            if (sub < 3) {
                // lanes 0,1,2 cover lsum[0..10] + count at [11] in one v4 RED
                const float b0 = (sub == 0) ? aj[0] : (sub == 1) ? aj[4] : aj[8];
                const float b1 = (sub == 0) ? aj[1] : (sub == 1) ? aj[5] : aj[9];
                const float b2 = (sub == 0) ? aj[2] : (sub == 1) ? aj[6] : aj[10];
                const float b3 = (sub == 0) ? aj[3] : (sub == 1) ? aj[7] : 1.0f;
                red_add_v4(&g_lsum[(size_t)sd.y * 12 + sub * 4], b0, b1, b2, b3);
            } else if (sub == 3) {
                atomicAdd(&g_denom[sd.y], ex);
            }
        }
    }
}

// ---------------------------------------------------------------------------
// Finalize: 2 nodes per warp (16 lanes x 4 cols). Self-loop term + normalize.
// ---------------------------------------------------------------------------
__global__ __launch_bounds__(256) void final_kernel(
    const float* __restrict__ We, const float* __restrict__ att,
    float* __restrict__ out, int n)
{
    const int lane   = threadIdx.x & 31;
    const int half   = lane >> 4;
    const int sub    = lane & 15;
    const int cb     = sub * 4;
    const int warp   = (blockIdx.x * blockDim.x + threadIdx.x) >> 5;
    const int nwarps = (gridDim.x * blockDim.x) >> 5;

    float4 wev[D_EDGE];
#pragma unroll
    for (int j = 0; j < D_EDGE; j++)
        wev[j] = *reinterpret_cast<const float4*>(We + j * D_OUT + cb);
    const float4 at = *reinterpret_cast<const float4*>(att + cb);

    for (int i0 = warp * 2; i0 < n; i0 += nwarps * 2) {
        const int  i     = i0 + half;
        const bool valid = (i < n);
        const int  ic    = valid ? i : i0;

        const float4* lp = reinterpret_cast<const float4*>(g_lsum + (size_t)ic * 12);
        const float4 q0 = lp[0];
        const float4 q1 = lp[1];
        const float4 q2 = lp[2];
        const float inv_deg = 1.0f / fmaxf(q2.w, 1.0f);

        float e0c = q0.x*wev[0].x + q0.y*wev[1].x + q0.z*wev[2].x + q0.w*wev[3].x
                  + q1.x*wev[4].x + q1.y*wev[5].x + q1.z*wev[6].x + q1.w*wev[7].x
                  + q2.x*wev[8].x + q2.y*wev[9].x + q2.z*wev[10].x;
        float e1c = q0.x*wev[0].y + q0.y*wev[1].y + q0.z*wev[2].y + q0.w*wev[3].y
                  + q1.x*wev[4].y + q1.y*wev[5].y + q1.z*wev[6].y + q1.w*wev[7].y
                  + q2.x*wev[8].y + q2.y*wev[9].y + q2.z*wev[10].y;
        float e2c = q0.x*wev[0].z + q0.y*wev[1].z + q0.z*wev[2].z + q0.w*wev[3].z
                  + q1.x*wev[4].z + q1.y*wev[5].z + q1.z*wev[6].z + q1.w*wev[7].z
                  + q2.x*wev[8].z + q2.y*wev[9].z + q2.z*wev[10].z;
        float e3c = q0.x*wev[0].w + q0.y*wev[1].w + q0.z*wev[2].w + q0.w*wev[3].w
                  + q1.x*wev[4].w + q1.y*wev[5].w + q1.z*wev[6].w + q1.w*wev[7].w
                  + q2.x*wev[8].w + q2.y*wev[9].w + q2.z*wev[10].w;   // FIXED: q2.z (was q2.w = deg)
        e0c *= inv_deg; e1c *= inv_deg; e2c *= inv_deg; e3c *= inv_deg;

        const float4 vl = *reinterpret_cast<const float4*>(g_xl + (size_t)ic * D_OUT + cb);
        const float4 vr = *reinterpret_cast<const float4*>(g_xr + (size_t)ic * D_OUT + cb);

        float m0 = vl.x + vr.x + e0c;
        float m1 = vl.y + vr.y + e1c;
        float m2 = vl.z + vr.z + e2c;
        float m3 = vl.w + vr.w + e3c;
        m0 = (m0 >= 0.f) ? m0 : NEG_SLOPE * m0;
        m1 = (m1 >= 0.f) ? m1 : NEG_SLOPE * m1;
        m2 = (m2 >= 0.f) ? m2 : NEG_SLOPE * m2;
        m3 = (m3 >= 0.f) ? m3 : NEG_SLOPE * m3;
        float p = m0 * at.x + m1 * at.y + m2 * at.z + m3 * at.w;
#pragma unroll
        for (int o = 8; o > 0; o >>= 1)
            p += __shfl_xor_sync(0xffffffffu, p, o);
        const float ex = __expf(p);

        if (valid) {
            const float invd = 1.0f / (g_denom[ic] + ex);
            float* op = out + (size_t)ic * D_OUT + cb;
            float4 o = *reinterpret_cast<float4*>(op);
            o.x = (o.x + ex * vl.x) * invd;
            o.y = (o.y + ex * vl.y) * invd;
            o.z = (o.z + ex * vl.z) * invd;
            o.w = (o.w + ex * vl.w) * invd;
            *reinterpret_cast<float4*>(op) = o;
        }
    }
}

// ---------------------------------------------------------------------------
extern "C" void kernel_launch(void* const* d_in, const int* in_sizes, int n_in,
                              void* d_out, int out_size)
{
    const float *x = nullptr, *ea = nullptr, *Wl = nullptr, *Wr = nullptr;
    const float *We = nullptr, *att = nullptr;
    const int   *ei = nullptr;
    long long E = 0;
    int n = 0;

    for (int i = 0; i < n_in; i++) {               // pass 1: edge_attr
        long long s = in_sizes[i];
        if (s > 100000 && s % D_EDGE == 0) { ea = (const float*)d_in[i]; E = s / D_EDGE; }
    }
    for (int i = 0; i < n_in; i++) {               // pass 2: everything else
        long long s = in_sizes[i];
        const void* p = d_in[i];
        if (p == (const void*)ea) continue;
        if      (E > 0 && (s == 2 * E || s == 4 * E)) { ei = (const int*)p; }
        else if (s == D_IN * D_OUT)   { if (!Wl) Wl = (const float*)p; else Wr = (const float*)p; }
        else if (s == D_EDGE * D_OUT) { We  = (const float*)p; }
        else if (s == D_OUT)          { att = (const float*)p; }
        else if (s > 100000 && s % D_IN == 0) { x = (const float*)p; n = (int)(s / D_IN); }
    }

    float* out = (float*)d_out;
    const int total_out = out_size;

    if (!x || !ea || !ei || !Wl || !Wr || !We || !att || n <= 0 || E <= 0 ||
        n > NMAX || E > EMAX) {
        set_diag_kernel<<<1, 32>>>(8);
        diag_apply_kernel<<<512, 256>>>(out, total_out);
        return;
    }
    const int Ei = (int)E;

    init_kernel<<<1024, 256>>>(out, total_out, ei, Ei, n);
    decode_kernel<<<512, 256>>>(ei, Ei, n);

    gemm_kernel<<<(n + 127) / 128, 256>>>(x, Wl, n, 0);  // -> g_xl
    gemm_kernel<<<(n + 127) / 128, 256>>>(x, Wr, n, 1);  // -> g_xr

    edge_kernel<<<4096, 256>>>(ea, We, att, out, Ei);
    final_kernel<<<2048, 256>>>(We, att, out, n);

    diag_apply_kernel<<<512, 256>>>(out, total_out);
}